// round 15
// baseline (speedup 1.0000x reference)
#include <cuda_runtime.h>
#include <math.h>
#include <stdint.h>

#define NN 2048
#define TT 64
#define FF 16
#define HH 64
#define LL 16
#define KK 10
#define NKEYS (NN*LL)            // 32768
#define KBLOCKS 8
#define KEYS_PER_KB (NKEYS/KBLOCKS)  // 4096
#define TILE_KEYS 128
#define NQUART 4
#define CAND_PER_ROW (KBLOCKS*NQUART*KK)   // 320

// ---------------- scratch (static device memory; no allocation) ----------------
__device__ float g_htail[NN*LL*HH];        // last-16 hidden states
__device__ float g_q[NN*HH];               // queries
__device__ float g_keysT[HH*NKEYS];        // projected keys, TRANSPOSED [h][key]
__device__ float g_pv[NN*CAND_PER_ROW];    // partial top-k values
__device__ int   g_pi[NN*CAND_PER_ROW];    // partial top-k indices

// ---------------- packed fp32x2 helpers ----------------
typedef unsigned long long u64t;
__device__ __forceinline__ void ffma2(u64t &d, u64t a, u64t b) {
    asm("fma.rn.f32x2 %0, %1, %2, %3;" : "=l"(d) : "l"(a), "l"(b), "l"(d));
}
__device__ __forceinline__ float f2sum(u64t v) {
    return __uint_as_float((uint32_t)v) + __uint_as_float((uint32_t)(v >> 32));
}
__device__ __forceinline__ u64t pack2(float a) {
    u64t r;
    asm("mov.b64 %0, {%1, %1};" : "=l"(r) : "f"(a));
    return r;
}
__device__ __forceinline__ float f2lo(u64t v) { return __uint_as_float((uint32_t)v); }
__device__ __forceinline__ float f2hi(u64t v) { return __uint_as_float((uint32_t)(v >> 32)); }

// ============================ K1: fused GRU (xp computed in-loop) — R13 version ============================
#define WS 66
#define WSX 20
#define GRU_SMEM_FLOATS (192*WS + 16*WS + 192*WSX + 2*16*WSX + 192 + 192)

__global__ void __launch_bounds__(256, 1) gru_kernel(
    const float* __restrict__ x,
    const float* __restrict__ Wih, const float* __restrict__ Whh,
    const float* __restrict__ bih, const float* __restrict__ bhh)
{
    extern __shared__ float sm[];
    float* sWhh = sm;                       // 192*66
    float* sh   = sWhh + 192*WS;            // 16*66
    float* sWih = sh + 16*WS;               // 192*20
    float* sxt  = sWih + 192*WSX;           // 2 x 16*20 (double-buffered x_t)
    float* sbih = sxt + 2*16*WSX;           // 192
    float* sbhh = sbih + 192;               // 192

    const int tid = threadIdx.x;
    const int n0  = blockIdx.x * 16;

    for (int i = tid; i < 192*64; i += 256) { int j = i >> 6, k = i & 63; sWhh[j*WS + k] = Whh[i]; }
    for (int i = tid; i < 192*16; i += 256) { int j = i >> 4, k = i & 15; sWih[j*WSX + k] = Wih[i]; }
    if (tid < 192) { sbih[tid] = bih[tid]; sbhh[tid] = bhh[tid]; }
    for (int i = tid; i < 16*WS; i += 256) sh[i] = 0.0f;
    {
        int r = tid >> 4, f = tid & 15;
        sxt[r*WSX + f] = x[((n0 + r)*TT + 0)*FF + f];
    }
    __syncthreads();

    const int jl = tid & 63;
    const int rb = tid >> 6;

    const float bi_r = sbih[jl],       bh_r = sbhh[jl];
    const float bi_z = sbih[64 + jl],  bh_z = sbhh[64 + jl];
    const float bi_n = sbih[128 + jl], bh_n = sbhh[128 + jl];

    for (int t = 0; t < TT; ++t) {
        const float* sxc = &sxt[(t & 1)*16*WSX];

        int tn = (t + 1 < TT) ? (t + 1) : (TT - 1);
        float xnext = x[((n0 + (tid >> 4))*TT + tn)*FF + (tid & 15)];

        // gx = x_t @ Wih^T  (K=16)
        u64t accx[4][3];
        #pragma unroll
        for (int i = 0; i < 4; ++i)
            #pragma unroll
            for (int u = 0; u < 3; ++u) accx[i][u] = 0;
        #pragma unroll
        for (int kc = 0; kc < 16; kc += 4) {
            u64t wa[3], wb[3];
            #pragma unroll
            for (int u = 0; u < 3; ++u) {
                const float* wp = &sWih[(jl + 64*u)*WSX + kc];
                wa[u] = *(const u64t*)wp;
                wb[u] = *(const u64t*)(wp + 2);
            }
            #pragma unroll
            for (int i = 0; i < 4; ++i) {
                const float* xp = &sxc[(rb*4 + i)*WSX + kc];
                u64t xa = *(const u64t*)xp;
                u64t xb = *(const u64t*)(xp + 2);
                #pragma unroll
                for (int u = 0; u < 3; ++u) {
                    ffma2(accx[i][u], xa, wa[u]);
                    ffma2(accx[i][u], xb, wb[u]);
                }
            }
        }

        // gh = h @ Whh^T  (K=64)
        u64t acc2[4][3];
        #pragma unroll
        for (int i = 0; i < 4; ++i)
            #pragma unroll
            for (int u = 0; u < 3; ++u) acc2[i][u] = 0;
        #pragma unroll
        for (int kc = 0; kc < 64; kc += 4) {
            u64t wa[3], wb[3];
            #pragma unroll
            for (int u = 0; u < 3; ++u) {
                const float* wp = &sWhh[(jl + 64*u)*WS + kc];
                wa[u] = *(const u64t*)wp;
                wb[u] = *(const u64t*)(wp + 2);
            }
            #pragma unroll
            for (int i = 0; i < 4; ++i) {
                const float* hp = &sh[(rb*4 + i)*WS + kc];
                u64t ha = *(const u64t*)hp;
                u64t hb = *(const u64t*)(hp + 2);
                #pragma unroll
                for (int u = 0; u < 3; ++u) {
                    ffma2(acc2[i][u], ha, wa[u]);
                    ffma2(acc2[i][u], hb, wb[u]);
                }
            }
        }

        sxt[((t + 1) & 1)*16*WSX + (tid >> 4)*WSX + (tid & 15)] = xnext;
        __syncthreads();   // h and x_t fully consumed; x_{t+1} visible next step

        #pragma unroll
        for (int i = 0; i < 4; ++i) {
            int r = rb*4 + i;
            float xr = f2sum(accx[i][0]) + bi_r;
            float xz = f2sum(accx[i][1]) + bi_z;
            float xn = f2sum(accx[i][2]) + bi_n;
            float hr = f2sum(acc2[i][0]) + bh_r;
            float hz = f2sum(acc2[i][1]) + bh_z;
            float hn = f2sum(acc2[i][2]) + bh_n;
            float rg = 1.0f / (1.0f + __expf(-(xr + hr)));
            float zg = 1.0f / (1.0f + __expf(-(xz + hz)));
            float targ = xn + rg * hn;
            float e2 = __expf(2.0f * targ);
            float ng = 1.0f - 2.0f / (e2 + 1.0f);
            float ho = sh[r*WS + jl];
            float hnew = (1.0f - zg) * ng + zg * ho;
            sh[r*WS + jl] = hnew;
            if (t >= TT - LL)
                g_htail[((n0 + r)*LL + (t - (TT - LL)))*HH + jl] = hnew;
        }
        __syncthreads();
    }
}

// ============================ K2: q/k projections (keys written transposed) ============================
__global__ void __launch_bounds__(256) qk_kernel(const float* __restrict__ Wq,
                                                 const float* __restrict__ Wk)
{
    __shared__ float sWq[64*68];
    __shared__ float sWk[64*68];
    __shared__ float sht[16*68];
    const int tid = threadIdx.x;
    const int n   = blockIdx.x;

    for (int i = tid; i < 64*64; i += 256) { int j = i >> 6, k = i & 63; sWq[j*68+k] = Wq[i]; sWk[j*68+k] = Wk[i]; }
    for (int i = tid; i < 16*64; i += 256) { int l = i >> 6, k = i & 63; sht[l*68+k] = g_htail[(n*16 + l)*64 + k]; }
    __syncthreads();

    const int tx = tid & 15, l = tid >> 4;
    float acc[4] = {0.f, 0.f, 0.f, 0.f};
    #pragma unroll
    for (int k = 0; k < 64; k += 4) {
        float4 hv = *(const float4*)&sht[l*68 + k];
        #pragma unroll
        for (int u = 0; u < 4; ++u) {
            float4 wv = *(const float4*)&sWk[(tx + 16*u)*68 + k];
            acc[u] = fmaf(hv.x, wv.x, fmaf(hv.y, wv.y, fmaf(hv.z, wv.z, fmaf(hv.w, wv.w, acc[u]))));
        }
    }
    #pragma unroll
    for (int u = 0; u < 4; ++u)
        g_keysT[(tx + 16*u)*NKEYS + n*16 + l] = acc[u];

    if (tid < 64) {
        float a = 0.f;
        #pragma unroll
        for (int k = 0; k < 64; k += 4) {
            float4 hv = *(const float4*)&sht[15*68 + k];
            float4 wv = *(const float4*)&sWq[tid*68 + k];
            a = fmaf(hv.x, wv.x, fmaf(hv.y, wv.y, fmaf(hv.z, wv.z, fmaf(hv.w, wv.w, a))));
        }
        g_q[n*64 + tid] = a;
    }
}

// ============================ K3: f32x2 GEMM + lock-free 4-way top-k (R8/R13 structure, fmax-group scan) ============================
#define WSQ 68    // sq row stride
#define WKT 132   // skt row stride: [kc][col]
#define SST 129   // score tile stride (odd: conflict-free scan)
#define K3_SMEM_FLOATS (64*WSQ + 64*WKT + 64*SST)
#define K3_SMEM_BYTES (K3_SMEM_FLOATS*4)

__global__ void __launch_bounds__(256, 2) scores_topk_kernel()
{
    extern __shared__ float sm[];
    float* sq  = sm;                 // 64 x 68
    float* skt = sq + 64*WSQ;        // 64 x 132 (transposed key tile [kc][col])
    float* sst = skt + 64*WKT;       // 64 x 129 (score tile [row][col])

    const int tid = threadIdx.x;
    const int qb  = blockIdx.x;        // 0..31
    const int kb  = blockIdx.y;        // 0..7

    // load 64 q rows
    for (int i = tid; i < 64*16; i += 256) {
        int r = i >> 4, c = (i & 15)*4;
        *(float4*)&sq[r*WSQ + c] = *(const float4*)&g_q[(qb*64 + r)*HH + c];
    }

    const int tx = tid & 15, ty = tid >> 4;
    const int kbase0 = kb * KEYS_PER_KB;

    // scan ownership: row = tid & 63, column quarter = tid >> 6
    const int srow  = tid & 63;
    const int squat = tid >> 6;
    const int qrow_s = qb*64 + srow;
    const int masklo = qrow_s*16;

    float tv[10]; int ti[10]; float thr = -INFINITY;
    #pragma unroll
    for (int e = 0; e < 10; ++e) { tv[e] = -INFINITY; ti[e] = 0; }

    for (int tt = 0; tt < KEYS_PER_KB / TILE_KEYS; ++tt) {
        const int kbase = kbase0 + tt*TILE_KEYS;

        // load transposed key tile
        for (int i = tid; i < 64*32; i += 256) {
            int h = i >> 5, c = (i & 31)*4;
            *(float4*)&skt[h*WKT + c] = *(const float4*)&g_keysT[h*NKEYS + kbase + c];
        }
        __syncthreads();   // skt ready AND all prior-tile scans complete

        // GEMM: 4 rows x 4 col-pairs, f32x2 accumulate
        u64t acc2[4][4];
        #pragma unroll
        for (int i = 0; i < 4; ++i)
            #pragma unroll
            for (int u = 0; u < 4; ++u) acc2[i][u] = 0;

        #pragma unroll 8
        for (int kc = 0; kc < 64; kc += 2) {
            u64t kf0[4], kf1[4];
            #pragma unroll
            for (int u = 0; u < 4; ++u) {
                kf0[u] = *(const u64t*)&skt[kc*WKT + 2*(tx + 16*u)];
                kf1[u] = *(const u64t*)&skt[(kc+1)*WKT + 2*(tx + 16*u)];
            }
            #pragma unroll
            for (int i = 0; i < 4; ++i) {
                float2 qv = *(const float2*)&sq[(ty + 16*i)*WSQ + kc];
                u64t qa = pack2(qv.x);
                u64t qc = pack2(qv.y);
                #pragma unroll
                for (int u = 0; u < 4; ++u) {
                    ffma2(acc2[i][u], qa, kf0[u]);
                    ffma2(acc2[i][u], qc, kf1[u]);
                }
            }
        }

        // stage scores to shared
        #pragma unroll
        for (int i = 0; i < 4; ++i) {
            int r = ty + 16*i;
            #pragma unroll
            for (int u = 0; u < 4; ++u) {
                int c = 2*(tx + 16*u);
                sst[r*SST + c]     = f2lo(acc2[i][u]);
                sst[r*SST + c + 1] = f2hi(acc2[i][u]);
            }
        }
        __syncthreads();

        // scan: fmax-grouped (4 elems/group), scalar loads (stride 129, conflict-free)
        {
            const int cb = kbase + 32*squat;
            const float* rowp = &sst[srow*SST + 32*squat];
            const int lo = masklo - cb;
            #pragma unroll
            for (int c4 = 0; c4 < 8; ++c4) {
                float v0 = rowp[c4*4 + 0];
                float v1 = rowp[c4*4 + 1];
                float v2 = rowp[c4*4 + 2];
                float v3 = rowp[c4*4 + 3];
                float m = fmaxf(fmaxf(v0, v1), fmaxf(v2, v3));
                if (m > thr) {
                    float vals[4] = {v0, v1, v2, v3};
                    #pragma unroll
                    for (int j = 0; j < 4; ++j) {
                        int c = c4*4 + j;
                        if (vals[j] > thr && (unsigned)(c - lo) >= 16u) {
                            int mp = 0; float mv = tv[0];
                            #pragma unroll
                            for (int e = 1; e < 10; ++e) if (tv[e] < mv) { mv = tv[e]; mp = e; }
                            #pragma unroll
                            for (int e = 0; e < 10; ++e) if (e == mp) { tv[e] = vals[j]; ti[e] = cb + c; }
                            float nm = tv[0];
                            #pragma unroll
                            for (int e = 1; e < 10; ++e) nm = fminf(nm, tv[e]);
                            thr = nm;
                        }
                    }
                }
            }
        }
        // no barrier: next iteration's post-load barrier protects sst
    }

    {
        float* pv = &g_pv[qrow_s*CAND_PER_ROW + kb*(NQUART*KK) + squat*KK];
        int*   pi = &g_pi[qrow_s*CAND_PER_ROW + kb*(NQUART*KK) + squat*KK];
        #pragma unroll
        for (int e = 0; e < 10; ++e) { pv[e] = tv[e]; pi[e] = ti[e]; }
    }
}

// ============================ K4: merge (320 cands) + softmax + gather + MLP ============================
__global__ void __launch_bounds__(256) final_kernel(
    const float* __restrict__ x,
    const float* __restrict__ W1, const float* __restrict__ b1,
    const float* __restrict__ W2, const float* __restrict__ b2,
    float* __restrict__ out)
{
    const int warp = threadIdx.x >> 5, lane = threadIdx.x & 31;
    const int n = blockIdx.x * 8 + warp;

    float cv[10]; int ci[10];
    #pragma unroll
    for (int s = 0; s < 10; ++s) {
        int c = lane + 32*s;
        cv[s] = g_pv[n*CAND_PER_ROW + c];
        ci[s] = g_pi[n*CAND_PER_ROW + c];
    }

    float topv[10]; int topi[10];
    #pragma unroll
    for (int it = 0; it < 10; ++it) {
        float bv = cv[0]; int bi = ci[0];
        #pragma unroll
        for (int s = 1; s < 10; ++s)
            if (cv[s] > bv || (cv[s] == bv && ci[s] < bi)) { bv = cv[s]; bi = ci[s]; }
        #pragma unroll
        for (int off = 16; off; off >>= 1) {
            float ov = __shfl_xor_sync(0xffffffffu, bv, off);
            int   oi = __shfl_xor_sync(0xffffffffu, bi, off);
            if (ov > bv || (ov == bv && oi < bi)) { bv = ov; bi = oi; }
        }
        topv[it] = bv; topi[it] = bi;
        #pragma unroll
        for (int s = 0; s < 10; ++s)
            if (ci[s] == bi) { cv[s] = -INFINITY; ci[s] = -2000 - s; }
    }

    float w[10]; float sumw = 0.0f;
    #pragma unroll
    for (int e = 0; e < 10; ++e) { w[e] = __expf(topv[e] - topv[0]); sumw += w[e]; }
    float inv = 1.0f / sumw;

    if (lane < 16) {
        float wf = 0.0f;
        #pragma unroll
        for (int e = 0; e < 10; ++e) {
            int m  = topi[e] >> 4;
            int ti2 = 48 + (topi[e] & 15);
            wf = fmaf(w[e] * inv, x[(m*TT + ti2)*FF + lane], wf);
        }
        float hid = b1[lane];
        #pragma unroll
        for (int f = 0; f < 16; ++f)
            hid = fmaf(W1[lane*16 + f], __shfl_sync(0xffffu, wf, f), hid);
        hid = hid > 0.0f ? hid : 0.01f * hid;
        float val = hid * W2[lane];
        #pragma unroll
        for (int off = 8; off; off >>= 1)
            val += __shfl_xor_sync(0xffffu, val, off);
        if (lane == 0) out[n] = val + b2[0];
    }
}

// ============================ launch ============================
extern "C" void kernel_launch(void* const* d_in, const int* in_sizes, int n_in,
                              void* d_out, int out_size)
{
    const float* x   = (const float*)d_in[0];
    const float* Wih = (const float*)d_in[1];
    const float* Whh = (const float*)d_in[2];
    const float* bih = (const float*)d_in[3];
    const float* bhh = (const float*)d_in[4];
    const float* Wq  = (const float*)d_in[5];
    const float* Wk  = (const float*)d_in[6];
    const float* W1  = (const float*)d_in[7];
    const float* b1  = (const float*)d_in[8];
    const float* W2  = (const float*)d_in[9];
    const float* b2  = (const float*)d_in[10];
    float* out = (float*)d_out;

    const int gru_smem = GRU_SMEM_FLOATS * 4;
    cudaFuncSetAttribute(gru_kernel, cudaFuncAttributeMaxDynamicSharedMemorySize, gru_smem);
    cudaFuncSetAttribute(scores_topk_kernel, cudaFuncAttributeMaxDynamicSharedMemorySize, K3_SMEM_BYTES);

    gru_kernel<<<NN/16, 256, gru_smem>>>(x, Wih, Whh, bih, bhh);
    qk_kernel<<<NN, 256>>>(Wq, Wk);
    dim3 g3(NN/64, KBLOCKS);
    scores_topk_kernel<<<g3, 256, K3_SMEM_BYTES>>>();
    final_kernel<<<NN/8, 256>>>(x, W1, b1, W2, b2, out);
}

// round 16
// speedup vs baseline: 1.7116x; 1.7116x over previous
#include <cuda_runtime.h>
#include <math.h>
#include <stdint.h>

#define NN 2048
#define TT 64
#define FF 16
#define HH 64
#define LL 16
#define KK 10
#define NKEYS (NN*LL)            // 32768
#define KBLOCKS 8
#define KEYS_PER_KB (NKEYS/KBLOCKS)  // 4096
#define TILE_KEYS 128
#define NQUART 4
#define CAND_PER_ROW (KBLOCKS*NQUART*KK)   // 320

// ---------------- scratch (static device memory; no allocation) ----------------
__device__ float g_q[NN*HH];               // queries
__device__ float g_keysT[HH*NKEYS];        // projected keys, TRANSPOSED [h][key]
__device__ float g_pv[NN*CAND_PER_ROW];    // partial top-k values
__device__ int   g_pi[NN*CAND_PER_ROW];    // partial top-k indices

// ---------------- packed fp32x2 helpers ----------------
typedef unsigned long long u64t;
__device__ __forceinline__ void ffma2(u64t &d, u64t a, u64t b) {
    asm("fma.rn.f32x2 %0, %1, %2, %3;" : "=l"(d) : "l"(a), "l"(b), "l"(d));
}
__device__ __forceinline__ float f2sum(u64t v) {
    return __uint_as_float((uint32_t)v) + __uint_as_float((uint32_t)(v >> 32));
}
__device__ __forceinline__ u64t pack2(float a) {
    u64t r;
    asm("mov.b64 %0, {%1, %1};" : "=l"(r) : "f"(a));
    return r;
}
__device__ __forceinline__ float f2lo(u64t v) { return __uint_as_float((uint32_t)v); }
__device__ __forceinline__ float f2hi(u64t v) { return __uint_as_float((uint32_t)(v >> 32)); }

// ============================ K1: fused GRU + q/k projection epilogue ============================
// 128 blocks x 256 threads; block owns 16 samples. htail kept in SHARED; qk fused.
#define WS 66
#define WSX 20
#define WHT 68
#define GRU_SMEM_FLOATS (192*WS + 16*WS + 192*WSX + 2*16*WSX + 192 + 192 + 256*WHT + 64*68 + 64*68)

__global__ void __launch_bounds__(256, 1) gru_kernel(
    const float* __restrict__ x,
    const float* __restrict__ Wih, const float* __restrict__ Whh,
    const float* __restrict__ bih, const float* __restrict__ bhh,
    const float* __restrict__ Wq,  const float* __restrict__ Wk)
{
    extern __shared__ float sm[];
    float* sWhh = sm;                       // 192*66
    float* sh   = sWhh + 192*WS;            // 16*66
    float* sWih = sh + 16*WS;               // 192*20
    float* sxt  = sWih + 192*WSX;           // 2 x 16*20 (double-buffered x_t)
    float* sbih = sxt + 2*16*WSX;           // 192
    float* sbhh = sbih + 192;               // 192
    float* sht  = sbhh + 192;               // 256*68 (16 samples x 16 lags)
    float* sWq  = sht + 256*WHT;            // 64*68
    float* sWk  = sWq + 64*68;              // 64*68

    const int tid = threadIdx.x;
    const int n0  = blockIdx.x * 16;

    for (int i = tid; i < 192*64; i += 256) { int j = i >> 6, k = i & 63; sWhh[j*WS + k] = Whh[i]; }
    for (int i = tid; i < 192*16; i += 256) { int j = i >> 4, k = i & 15; sWih[j*WSX + k] = Wih[i]; }
    for (int i = tid; i < 64*64; i += 256) { int j = i >> 6, k = i & 63; sWq[j*68+k] = Wq[i]; sWk[j*68+k] = Wk[i]; }
    if (tid < 192) { sbih[tid] = bih[tid]; sbhh[tid] = bhh[tid]; }
    for (int i = tid; i < 16*WS; i += 256) sh[i] = 0.0f;
    {
        int r = tid >> 4, f = tid & 15;
        sxt[r*WSX + f] = x[((n0 + r)*TT + 0)*FF + f];
    }
    __syncthreads();

    const int jl = tid & 63;
    const int rb = tid >> 6;

    const float bi_r = sbih[jl],       bh_r = sbhh[jl];
    const float bi_z = sbih[64 + jl],  bh_z = sbhh[64 + jl];
    const float bi_n = sbih[128 + jl], bh_n = sbhh[128 + jl];

    for (int t = 0; t < TT; ++t) {
        const float* sxc = &sxt[(t & 1)*16*WSX];

        int tn = (t + 1 < TT) ? (t + 1) : (TT - 1);
        float xnext = x[((n0 + (tid >> 4))*TT + tn)*FF + (tid & 15)];

        // gx = x_t @ Wih^T  (K=16)
        u64t accx[4][3];
        #pragma unroll
        for (int i = 0; i < 4; ++i)
            #pragma unroll
            for (int u = 0; u < 3; ++u) accx[i][u] = 0;
        #pragma unroll
        for (int kc = 0; kc < 16; kc += 4) {
            u64t wa[3], wb[3];
            #pragma unroll
            for (int u = 0; u < 3; ++u) {
                const float* wp = &sWih[(jl + 64*u)*WSX + kc];
                wa[u] = *(const u64t*)wp;
                wb[u] = *(const u64t*)(wp + 2);
            }
            #pragma unroll
            for (int i = 0; i < 4; ++i) {
                const float* xp = &sxc[(rb*4 + i)*WSX + kc];
                u64t xa = *(const u64t*)xp;
                u64t xb = *(const u64t*)(xp + 2);
                #pragma unroll
                for (int u = 0; u < 3; ++u) {
                    ffma2(accx[i][u], xa, wa[u]);
                    ffma2(accx[i][u], xb, wb[u]);
                }
            }
        }

        // gh = h @ Whh^T  (K=64)
        u64t acc2[4][3];
        #pragma unroll
        for (int i = 0; i < 4; ++i)
            #pragma unroll
            for (int u = 0; u < 3; ++u) acc2[i][u] = 0;
        #pragma unroll
        for (int kc = 0; kc < 64; kc += 4) {
            u64t wa[3], wb[3];
            #pragma unroll
            for (int u = 0; u < 3; ++u) {
                const float* wp = &sWhh[(jl + 64*u)*WS + kc];
                wa[u] = *(const u64t*)wp;
                wb[u] = *(const u64t*)(wp + 2);
            }
            #pragma unroll
            for (int i = 0; i < 4; ++i) {
                const float* hp = &sh[(rb*4 + i)*WS + kc];
                u64t ha = *(const u64t*)hp;
                u64t hb = *(const u64t*)(hp + 2);
                #pragma unroll
                for (int u = 0; u < 3; ++u) {
                    ffma2(acc2[i][u], ha, wa[u]);
                    ffma2(acc2[i][u], hb, wb[u]);
                }
            }
        }

        sxt[((t + 1) & 1)*16*WSX + (tid >> 4)*WSX + (tid & 15)] = xnext;
        __syncthreads();   // h and x_t fully consumed; x_{t+1} visible next step

        #pragma unroll
        for (int i = 0; i < 4; ++i) {
            int r = rb*4 + i;
            float xr = f2sum(accx[i][0]) + bi_r;
            float xz = f2sum(accx[i][1]) + bi_z;
            float xn = f2sum(accx[i][2]) + bi_n;
            float hr = f2sum(acc2[i][0]) + bh_r;
            float hz = f2sum(acc2[i][1]) + bh_z;
            float hn = f2sum(acc2[i][2]) + bh_n;
            float rg = 1.0f / (1.0f + __expf(-(xr + hr)));
            float zg = 1.0f / (1.0f + __expf(-(xz + hz)));
            float targ = xn + rg * hn;
            float e2 = __expf(2.0f * targ);
            float ng = 1.0f - 2.0f / (e2 + 1.0f);
            float ho = sh[r*WS + jl];
            float hnew = (1.0f - zg) * ng + zg * ho;
            sh[r*WS + jl] = hnew;
            if (t >= TT - LL)
                sht[(r*LL + (t - (TT - LL)))*WHT + jl] = hnew;   // shared, not gmem
        }
        __syncthreads();
    }

    // ---- fused q/k projection (mirrors the old qk_kernel body, 16 samples) ----
    const int tx2 = tid & 15, lg = tid >> 4;
    for (int blk = 0; blk < 16; ++blk) {
        const float* ht = &sht[(blk*LL + lg)*WHT];
        float acc[4] = {0.f, 0.f, 0.f, 0.f};
        #pragma unroll
        for (int k = 0; k < 64; k += 4) {
            float4 hv = *(const float4*)&ht[k];
            #pragma unroll
            for (int u = 0; u < 4; ++u) {
                float4 wv = *(const float4*)&sWk[(tx2 + 16*u)*68 + k];
                acc[u] = fmaf(hv.x, wv.x, fmaf(hv.y, wv.y, fmaf(hv.z, wv.z, fmaf(hv.w, wv.w, acc[u]))));
            }
        }
        #pragma unroll
        for (int u = 0; u < 4; ++u)
            g_keysT[(tx2 + 16*u)*NKEYS + (n0 + blk)*16 + lg] = acc[u];
    }
    {
        const int j = tid & 63, sg = tid >> 6;
        for (int ss = sg; ss < 16; ss += 4) {
            const float* ht = &sht[(ss*LL + 15)*WHT];
            float a = 0.f;
            #pragma unroll
            for (int k = 0; k < 64; k += 4) {
                float4 hv = *(const float4*)&ht[k];
                float4 wv = *(const float4*)&sWq[j*68 + k];
                a = fmaf(hv.x, wv.x, fmaf(hv.y, wv.y, fmaf(hv.z, wv.z, fmaf(hv.w, wv.w, a))));
            }
            g_q[(n0 + ss)*64 + j] = a;
        }
    }
}

// ============================ K3: f32x2 GEMM + lock-free 4-way top-k (R13 verbatim) ============================
#define WSQ 68    // sq row stride
#define WKT 132   // skt row stride: [kc][col]
#define SST 129   // score tile stride (odd)
#define K3_SMEM_FLOATS (64*WSQ + 64*WKT + 64*SST)
#define K3_SMEM_BYTES (K3_SMEM_FLOATS*4)

__global__ void __launch_bounds__(256, 2) scores_topk_kernel()
{
    extern __shared__ float sm[];
    float* sq  = sm;                 // 64 x 68
    float* skt = sq + 64*WSQ;        // 64 x 132 (transposed key tile [kc][col])
    float* sst = skt + 64*WKT;       // 64 x 129 (score tile [row][col])

    const int tid = threadIdx.x;
    const int qb  = blockIdx.x;        // 0..31
    const int kb  = blockIdx.y;        // 0..7

    // load 64 q rows
    for (int i = tid; i < 64*16; i += 256) {
        int r = i >> 4, c = (i & 15)*4;
        *(float4*)&sq[r*WSQ + c] = *(const float4*)&g_q[(qb*64 + r)*HH + c];
    }

    const int tx = tid & 15, ty = tid >> 4;
    const int kbase0 = kb * KEYS_PER_KB;

    // scan ownership: row = tid & 63, column quarter = tid >> 6
    const int srow  = tid & 63;
    const int squat = tid >> 6;
    const int qrow_s = qb*64 + srow;
    const int masklo = qrow_s*16;

    float tv[10]; int ti[10]; float thr = -INFINITY;
    #pragma unroll
    for (int e = 0; e < 10; ++e) { tv[e] = -INFINITY; ti[e] = 0; }

    for (int tt = 0; tt < KEYS_PER_KB / TILE_KEYS; ++tt) {
        const int kbase = kbase0 + tt*TILE_KEYS;

        // load transposed key tile
        for (int i = tid; i < 64*32; i += 256) {
            int h = i >> 5, c = (i & 31)*4;
            *(float4*)&skt[h*WKT + c] = *(const float4*)&g_keysT[h*NKEYS + kbase + c];
        }
        __syncthreads();   // skt ready AND all prior-tile scans complete

        // GEMM: 4 rows x 4 col-pairs, f32x2 accumulate
        u64t acc2[4][4];
        #pragma unroll
        for (int i = 0; i < 4; ++i)
            #pragma unroll
            for (int u = 0; u < 4; ++u) acc2[i][u] = 0;

        #pragma unroll 8
        for (int kc = 0; kc < 64; kc += 2) {
            u64t kf0[4], kf1[4];
            #pragma unroll
            for (int u = 0; u < 4; ++u) {
                kf0[u] = *(const u64t*)&skt[kc*WKT + 2*(tx + 16*u)];
                kf1[u] = *(const u64t*)&skt[(kc+1)*WKT + 2*(tx + 16*u)];
            }
            #pragma unroll
            for (int i = 0; i < 4; ++i) {
                float2 qv = *(const float2*)&sq[(ty + 16*i)*WSQ + kc];
                u64t qa = pack2(qv.x);
                u64t qc = pack2(qv.y);
                #pragma unroll
                for (int u = 0; u < 4; ++u) {
                    ffma2(acc2[i][u], qa, kf0[u]);
                    ffma2(acc2[i][u], qc, kf1[u]);
                }
            }
        }

        // stage scores to shared
        #pragma unroll
        for (int i = 0; i < 4; ++i) {
            int r = ty + 16*i;
            #pragma unroll
            for (int u = 0; u < 4; ++u) {
                int c = 2*(tx + 16*u);
                sst[r*SST + c]     = f2lo(acc2[i][u]);
                sst[r*SST + c + 1] = f2hi(acc2[i][u]);
            }
        }
        __syncthreads();

        // scan: all 256 threads; thread owns (row srow, 32-col quarter squat)
        {
            const int cb = kbase + 32*squat;
            const float* rowp = &sst[srow*SST + 32*squat];
            const int lo = masklo - cb;
            #pragma unroll 8
            for (int c = 0; c < 32; ++c) {
                float v = rowp[c];
                if (v > thr && (unsigned)(c - lo) >= 16u) {
                    int mp = 0; float mv = tv[0];
                    #pragma unroll
                    for (int e = 1; e < 10; ++e) if (tv[e] < mv) { mv = tv[e]; mp = e; }
                    #pragma unroll
                    for (int e = 0; e < 10; ++e) if (e == mp) { tv[e] = v; ti[e] = cb + c; }
                    float nm = tv[0];
                    #pragma unroll
                    for (int e = 1; e < 10; ++e) nm = fminf(nm, tv[e]);
                    thr = nm;
                }
            }
        }
        // no barrier: next iteration's post-load barrier protects sst
    }

    {
        float* pv = &g_pv[qrow_s*CAND_PER_ROW + kb*(NQUART*KK) + squat*KK];
        int*   pi = &g_pi[qrow_s*CAND_PER_ROW + kb*(NQUART*KK) + squat*KK];
        #pragma unroll
        for (int e = 0; e < 10; ++e) { pv[e] = tv[e]; pi[e] = ti[e]; }
    }
}

// ============================ K4: merge (320 cands) + softmax + gather + MLP ============================
__global__ void __launch_bounds__(256) final_kernel(
    const float* __restrict__ x,
    const float* __restrict__ W1, const float* __restrict__ b1,
    const float* __restrict__ W2, const float* __restrict__ b2,
    float* __restrict__ out)
{
    const int warp = threadIdx.x >> 5, lane = threadIdx.x & 31;
    const int n = blockIdx.x * 8 + warp;

    float cv[10]; int ci[10];
    #pragma unroll
    for (int s = 0; s < 10; ++s) {
        int c = lane + 32*s;
        cv[s] = g_pv[n*CAND_PER_ROW + c];
        ci[s] = g_pi[n*CAND_PER_ROW + c];
    }

    float topv[10]; int topi[10];
    #pragma unroll
    for (int it = 0; it < 10; ++it) {
        float bv = cv[0]; int bi = ci[0];
        #pragma unroll
        for (int s = 1; s < 10; ++s)
            if (cv[s] > bv || (cv[s] == bv && ci[s] < bi)) { bv = cv[s]; bi = ci[s]; }
        #pragma unroll
        for (int off = 16; off; off >>= 1) {
            float ov = __shfl_xor_sync(0xffffffffu, bv, off);
            int   oi = __shfl_xor_sync(0xffffffffu, bi, off);
            if (ov > bv || (ov == bv && oi < bi)) { bv = ov; bi = oi; }
        }
        topv[it] = bv; topi[it] = bi;
        #pragma unroll
        for (int s = 0; s < 10; ++s)
            if (ci[s] == bi) { cv[s] = -INFINITY; ci[s] = -2000 - s; }
    }

    float w[10]; float sumw = 0.0f;
    #pragma unroll
    for (int e = 0; e < 10; ++e) { w[e] = __expf(topv[e] - topv[0]); sumw += w[e]; }
    float inv = 1.0f / sumw;

    if (lane < 16) {
        float wf = 0.0f;
        #pragma unroll
        for (int e = 0; e < 10; ++e) {
            int m  = topi[e] >> 4;
            int ti2 = 48 + (topi[e] & 15);
            wf = fmaf(w[e] * inv, x[(m*TT + ti2)*FF + lane], wf);
        }
        float hid = b1[lane];
        #pragma unroll
        for (int f = 0; f < 16; ++f)
            hid = fmaf(W1[lane*16 + f], __shfl_sync(0xffffu, wf, f), hid);
        hid = hid > 0.0f ? hid : 0.01f * hid;
        float val = hid * W2[lane];
        #pragma unroll
        for (int off = 8; off; off >>= 1)
            val += __shfl_xor_sync(0xffffu, val, off);
        if (lane == 0) out[n] = val + b2[0];
    }
}

// ============================ launch ============================
extern "C" void kernel_launch(void* const* d_in, const int* in_sizes, int n_in,
                              void* d_out, int out_size)
{
    const float* x   = (const float*)d_in[0];
    const float* Wih = (const float*)d_in[1];
    const float* Whh = (const float*)d_in[2];
    const float* bih = (const float*)d_in[3];
    const float* bhh = (const float*)d_in[4];
    const float* Wq  = (const float*)d_in[5];
    const float* Wk  = (const float*)d_in[6];
    const float* W1  = (const float*)d_in[7];
    const float* b1  = (const float*)d_in[8];
    const float* W2  = (const float*)d_in[9];
    const float* b2  = (const float*)d_in[10];
    float* out = (float*)d_out;

    const int gru_smem = GRU_SMEM_FLOATS * 4;
    cudaFuncSetAttribute(gru_kernel, cudaFuncAttributeMaxDynamicSharedMemorySize, gru_smem);
    cudaFuncSetAttribute(scores_topk_kernel, cudaFuncAttributeMaxDynamicSharedMemorySize, K3_SMEM_BYTES);

    gru_kernel<<<NN/16, 256, gru_smem>>>(x, Wih, Whh, bih, bhh, Wq, Wk);
    dim3 g3(NN/64, KBLOCKS);
    scores_topk_kernel<<<g3, 256, K3_SMEM_BYTES>>>();
    final_kernel<<<NN/8, 256>>>(x, W1, b1, W2, b2, out);
}

// round 17
// speedup vs baseline: 1.7291x; 1.0102x over previous
#include <cuda_runtime.h>
#include <math.h>
#include <stdint.h>

#define NN 2048
#define TT 64
#define FF 16
#define HH 64
#define LL 16
#define KK 10
#define NKEYS (NN*LL)            // 32768
#define KBLOCKS 8
#define KEYS_PER_KB (NKEYS/KBLOCKS)  // 4096
#define TILE_KEYS 128
#define NQUART 4
#define CAND_PER_ROW (KBLOCKS*NQUART*KK)   // 320

// ---------------- scratch (static device memory; no allocation) ----------------
__device__ float g_q[NN*HH];               // queries
__device__ float g_keysT[HH*NKEYS];        // projected keys, TRANSPOSED [h][key]
__device__ float g_pv[NN*CAND_PER_ROW];    // partial top-k values
__device__ int   g_pi[NN*CAND_PER_ROW];    // partial top-k indices

// ---------------- packed fp32x2 helpers ----------------
typedef unsigned long long u64t;
__device__ __forceinline__ void ffma2(u64t &d, u64t a, u64t b) {
    asm("fma.rn.f32x2 %0, %1, %2, %3;" : "=l"(d) : "l"(a), "l"(b), "l"(d));
}
__device__ __forceinline__ float f2sum(u64t v) {
    return __uint_as_float((uint32_t)v) + __uint_as_float((uint32_t)(v >> 32));
}
__device__ __forceinline__ u64t pack2(float a) {
    u64t r;
    asm("mov.b64 %0, {%1, %1};" : "=l"(r) : "f"(a));
    return r;
}
__device__ __forceinline__ float f2lo(u64t v) { return __uint_as_float((uint32_t)v); }
__device__ __forceinline__ float f2hi(u64t v) { return __uint_as_float((uint32_t)(v >> 32)); }

// ============================ K1: fused GRU + q/k epilogue (h double-buffered, 1 barrier/step) ============================
#define WS 66
#define WSX 20
#define WHT 68
#define GRU_SMEM_FLOATS (192*WS + 2*16*WS + 192*WSX + 2*16*WSX + 192 + 192 + 256*WHT + 64*68 + 64*68)

__global__ void __launch_bounds__(256, 1) gru_kernel(
    const float* __restrict__ x,
    const float* __restrict__ Wih, const float* __restrict__ Whh,
    const float* __restrict__ bih, const float* __restrict__ bhh,
    const float* __restrict__ Wq,  const float* __restrict__ Wk)
{
    extern __shared__ float sm[];
    float* sWhh = sm;                       // 192*66
    float* sh   = sWhh + 192*WS;            // 2 x 16*66 (double-buffered h)
    float* sWih = sh + 2*16*WS;             // 192*20
    float* sxt  = sWih + 192*WSX;           // 2 x 16*20 (double-buffered x_t)
    float* sbih = sxt + 2*16*WSX;           // 192
    float* sbhh = sbih + 192;               // 192
    float* sht  = sbhh + 192;               // 256*68 (16 samples x 16 lags)
    float* sWq  = sht + 256*WHT;            // 64*68
    float* sWk  = sWq + 64*68;              // 64*68

    const int tid = threadIdx.x;
    const int n0  = blockIdx.x * 16;

    for (int i = tid; i < 192*64; i += 256) { int j = i >> 6, k = i & 63; sWhh[j*WS + k] = Whh[i]; }
    for (int i = tid; i < 192*16; i += 256) { int j = i >> 4, k = i & 15; sWih[j*WSX + k] = Wih[i]; }
    for (int i = tid; i < 64*64; i += 256) { int j = i >> 6, k = i & 63; sWq[j*68+k] = Wq[i]; sWk[j*68+k] = Wk[i]; }
    if (tid < 192) { sbih[tid] = bih[tid]; sbhh[tid] = bhh[tid]; }
    for (int i = tid; i < 16*WS; i += 256) sh[i] = 0.0f;     // buffer 0 (read at t=0)
    {
        int r = tid >> 4, f = tid & 15;
        sxt[r*WSX + f] = x[((n0 + r)*TT + 0)*FF + f];        // x_0 into buffer 0
    }
    __syncthreads();

    const int jl = tid & 63;
    const int rb = tid >> 6;

    const float bi_r = sbih[jl],       bh_r = sbhh[jl];
    const float bi_z = sbih[64 + jl],  bh_z = sbhh[64 + jl];
    const float bi_n = sbih[128 + jl], bh_n = sbhh[128 + jl];

    for (int t = 0; t < TT; ++t) {
        const int cur = t & 1, alt = cur ^ 1;
        const float* sxc = &sxt[cur*16*WSX];
        const float* shc = &sh[cur*16*WS];
        float* sha = &sh[alt*16*WS];

        int tn = (t + 1 < TT) ? (t + 1) : (TT - 1);
        float xnext = x[((n0 + (tid >> 4))*TT + tn)*FF + (tid & 15)];

        // gx = x_t @ Wih^T  (K=16)
        u64t accx[4][3];
        #pragma unroll
        for (int i = 0; i < 4; ++i)
            #pragma unroll
            for (int u = 0; u < 3; ++u) accx[i][u] = 0;
        #pragma unroll
        for (int kc = 0; kc < 16; kc += 4) {
            u64t wa[3], wb[3];
            #pragma unroll
            for (int u = 0; u < 3; ++u) {
                const float* wp = &sWih[(jl + 64*u)*WSX + kc];
                wa[u] = *(const u64t*)wp;
                wb[u] = *(const u64t*)(wp + 2);
            }
            #pragma unroll
            for (int i = 0; i < 4; ++i) {
                const float* xp = &sxc[(rb*4 + i)*WSX + kc];
                u64t xa = *(const u64t*)xp;
                u64t xb = *(const u64t*)(xp + 2);
                #pragma unroll
                for (int u = 0; u < 3; ++u) {
                    ffma2(accx[i][u], xa, wa[u]);
                    ffma2(accx[i][u], xb, wb[u]);
                }
            }
        }

        // gh = h @ Whh^T  (K=64)
        u64t acc2[4][3];
        #pragma unroll
        for (int i = 0; i < 4; ++i)
            #pragma unroll
            for (int u = 0; u < 3; ++u) acc2[i][u] = 0;
        #pragma unroll
        for (int kc = 0; kc < 64; kc += 4) {
            u64t wa[3], wb[3];
            #pragma unroll
            for (int u = 0; u < 3; ++u) {
                const float* wp = &sWhh[(jl + 64*u)*WS + kc];
                wa[u] = *(const u64t*)wp;
                wb[u] = *(const u64t*)(wp + 2);
            }
            #pragma unroll
            for (int i = 0; i < 4; ++i) {
                const float* hp = &shc[(rb*4 + i)*WS + kc];
                u64t ha = *(const u64t*)hp;
                u64t hb = *(const u64t*)(hp + 2);
                #pragma unroll
                for (int u = 0; u < 3; ++u) {
                    ffma2(acc2[i][u], ha, wa[u]);
                    ffma2(acc2[i][u], hb, wb[u]);
                }
            }
        }

        // update: all writes go to ALT buffers / disjoint regions (no reader this step)
        #pragma unroll
        for (int i = 0; i < 4; ++i) {
            int r = rb*4 + i;
            float xr = f2sum(accx[i][0]) + bi_r;
            float xz = f2sum(accx[i][1]) + bi_z;
            float xn = f2sum(accx[i][2]) + bi_n;
            float hr = f2sum(acc2[i][0]) + bh_r;
            float hz = f2sum(acc2[i][1]) + bh_z;
            float hn = f2sum(acc2[i][2]) + bh_n;
            float rg = 1.0f / (1.0f + __expf(-(xr + hr)));
            float zg = 1.0f / (1.0f + __expf(-(xz + hz)));
            float targ = xn + rg * hn;
            float e2 = __expf(2.0f * targ);
            float ng = 1.0f - 2.0f / (e2 + 1.0f);
            float ho = shc[r*WS + jl];
            float hnew = (1.0f - zg) * ng + zg * ho;
            sha[r*WS + jl] = hnew;
            if (t >= TT - LL)
                sht[(r*LL + (t - (TT - LL)))*WHT + jl] = hnew;
        }
        sxt[alt*16*WSX + (tid >> 4)*WSX + (tid & 15)] = xnext;
        __syncthreads();   // single barrier: alt buffers complete before next step reads
    }

    // ---- fused q/k projection (16 samples) ----
    const int tx2 = tid & 15, lg = tid >> 4;
    for (int blk = 0; blk < 16; ++blk) {
        const float* ht = &sht[(blk*LL + lg)*WHT];
        float acc[4] = {0.f, 0.f, 0.f, 0.f};
        #pragma unroll
        for (int k = 0; k < 64; k += 4) {
            float4 hv = *(const float4*)&ht[k];
            #pragma unroll
            for (int u = 0; u < 4; ++u) {
                float4 wv = *(const float4*)&sWk[(tx2 + 16*u)*68 + k];
                acc[u] = fmaf(hv.x, wv.x, fmaf(hv.y, wv.y, fmaf(hv.z, wv.z, fmaf(hv.w, wv.w, acc[u]))));
            }
        }
        #pragma unroll
        for (int u = 0; u < 4; ++u)
            g_keysT[(tx2 + 16*u)*NKEYS + (n0 + blk)*16 + lg] = acc[u];
    }
    {
        const int j = tid & 63, sg = tid >> 6;
        for (int ss = sg; ss < 16; ss += 4) {
            const float* ht = &sht[(ss*LL + 15)*WHT];
            float a = 0.f;
            #pragma unroll
            for (int k = 0; k < 64; k += 4) {
                float4 hv = *(const float4*)&ht[k];
                float4 wv = *(const float4*)&sWq[j*68 + k];
                a = fmaf(hv.x, wv.x, fmaf(hv.y, wv.y, fmaf(hv.z, wv.z, fmaf(hv.w, wv.w, a))));
            }
            g_q[(n0 + ss)*64 + j] = a;
        }
    }
}

// ============================ K3: f32x2 GEMM + lock-free 4-way top-k (R13 verbatim) ============================
#define WSQ 68    // sq row stride
#define WKT 132   // skt row stride: [kc][col]
#define SST 129   // score tile stride (odd)
#define K3_SMEM_FLOATS (64*WSQ + 64*WKT + 64*SST)
#define K3_SMEM_BYTES (K3_SMEM_FLOATS*4)

__global__ void __launch_bounds__(256, 2) scores_topk_kernel()
{
    extern __shared__ float sm[];
    float* sq  = sm;                 // 64 x 68
    float* skt = sq + 64*WSQ;        // 64 x 132 (transposed key tile [kc][col])
    float* sst = skt + 64*WKT;       // 64 x 129 (score tile [row][col])

    const int tid = threadIdx.x;
    const int qb  = blockIdx.x;        // 0..31
    const int kb  = blockIdx.y;        // 0..7

    // load 64 q rows
    for (int i = tid; i < 64*16; i += 256) {
        int r = i >> 4, c = (i & 15)*4;
        *(float4*)&sq[r*WSQ + c] = *(const float4*)&g_q[(qb*64 + r)*HH + c];
    }

    const int tx = tid & 15, ty = tid >> 4;
    const int kbase0 = kb * KEYS_PER_KB;

    // scan ownership: row = tid & 63, column quarter = tid >> 6
    const int srow  = tid & 63;
    const int squat = tid >> 6;
    const int qrow_s = qb*64 + srow;
    const int masklo = qrow_s*16;

    float tv[10]; int ti[10]; float thr = -INFINITY;
    #pragma unroll
    for (int e = 0; e < 10; ++e) { tv[e] = -INFINITY; ti[e] = 0; }

    for (int tt = 0; tt < KEYS_PER_KB / TILE_KEYS; ++tt) {
        const int kbase = kbase0 + tt*TILE_KEYS;

        // load transposed key tile
        for (int i = tid; i < 64*32; i += 256) {
            int h = i >> 5, c = (i & 31)*4;
            *(float4*)&skt[h*WKT + c] = *(const float4*)&g_keysT[h*NKEYS + kbase + c];
        }
        __syncthreads();   // skt ready AND all prior-tile scans complete

        // GEMM: 4 rows x 4 col-pairs, f32x2 accumulate
        u64t acc2[4][4];
        #pragma unroll
        for (int i = 0; i < 4; ++i)
            #pragma unroll
            for (int u = 0; u < 4; ++u) acc2[i][u] = 0;

        #pragma unroll 8
        for (int kc = 0; kc < 64; kc += 2) {
            u64t kf0[4], kf1[4];
            #pragma unroll
            for (int u = 0; u < 4; ++u) {
                kf0[u] = *(const u64t*)&skt[kc*WKT + 2*(tx + 16*u)];
                kf1[u] = *(const u64t*)&skt[(kc+1)*WKT + 2*(tx + 16*u)];
            }
            #pragma unroll
            for (int i = 0; i < 4; ++i) {
                float2 qv = *(const float2*)&sq[(ty + 16*i)*WSQ + kc];
                u64t qa = pack2(qv.x);
                u64t qc = pack2(qv.y);
                #pragma unroll
                for (int u = 0; u < 4; ++u) {
                    ffma2(acc2[i][u], qa, kf0[u]);
                    ffma2(acc2[i][u], qc, kf1[u]);
                }
            }
        }

        // stage scores to shared
        #pragma unroll
        for (int i = 0; i < 4; ++i) {
            int r = ty + 16*i;
            #pragma unroll
            for (int u = 0; u < 4; ++u) {
                int c = 2*(tx + 16*u);
                sst[r*SST + c]     = f2lo(acc2[i][u]);
                sst[r*SST + c + 1] = f2hi(acc2[i][u]);
            }
        }
        __syncthreads();

        // scan: all 256 threads; thread owns (row srow, 32-col quarter squat)
        {
            const int cb = kbase + 32*squat;
            const float* rowp = &sst[srow*SST + 32*squat];
            const int lo = masklo - cb;
            #pragma unroll 8
            for (int c = 0; c < 32; ++c) {
                float v = rowp[c];
                if (v > thr && (unsigned)(c - lo) >= 16u) {
                    int mp = 0; float mv = tv[0];
                    #pragma unroll
                    for (int e = 1; e < 10; ++e) if (tv[e] < mv) { mv = tv[e]; mp = e; }
                    #pragma unroll
                    for (int e = 0; e < 10; ++e) if (e == mp) { tv[e] = v; ti[e] = cb + c; }
                    float nm = tv[0];
                    #pragma unroll
                    for (int e = 1; e < 10; ++e) nm = fminf(nm, tv[e]);
                    thr = nm;
                }
            }
        }
        // no barrier: next iteration's post-load barrier protects sst
    }

    {
        float* pv = &g_pv[qrow_s*CAND_PER_ROW + kb*(NQUART*KK) + squat*KK];
        int*   pi = &g_pi[qrow_s*CAND_PER_ROW + kb*(NQUART*KK) + squat*KK];
        #pragma unroll
        for (int e = 0; e < 10; ++e) { pv[e] = tv[e]; pi[e] = ti[e]; }
    }
}

// ============================ K4: merge (320 cands) + softmax + gather + MLP ============================
__global__ void __launch_bounds__(256) final_kernel(
    const float* __restrict__ x,
    const float* __restrict__ W1, const float* __restrict__ b1,
    const float* __restrict__ W2, const float* __restrict__ b2,
    float* __restrict__ out)
{
    const int warp = threadIdx.x >> 5, lane = threadIdx.x & 31;
    const int n = blockIdx.x * 8 + warp;

    float cv[10]; int ci[10];
    #pragma unroll
    for (int s = 0; s < 10; ++s) {
        int c = lane + 32*s;
        cv[s] = g_pv[n*CAND_PER_ROW + c];
        ci[s] = g_pi[n*CAND_PER_ROW + c];
    }

    float topv[10]; int topi[10];
    #pragma unroll
    for (int it = 0; it < 10; ++it) {
        float bv = cv[0]; int bi = ci[0];
        #pragma unroll
        for (int s = 1; s < 10; ++s)
            if (cv[s] > bv || (cv[s] == bv && ci[s] < bi)) { bv = cv[s]; bi = ci[s]; }
        #pragma unroll
        for (int off = 16; off; off >>= 1) {
            float ov = __shfl_xor_sync(0xffffffffu, bv, off);
            int   oi = __shfl_xor_sync(0xffffffffu, bi, off);
            if (ov > bv || (ov == bv && oi < bi)) { bv = ov; bi = oi; }
        }
        topv[it] = bv; topi[it] = bi;
        #pragma unroll
        for (int s = 0; s < 10; ++s)
            if (ci[s] == bi) { cv[s] = -INFINITY; ci[s] = -2000 - s; }
    }

    float w[10]; float sumw = 0.0f;
    #pragma unroll
    for (int e = 0; e < 10; ++e) { w[e] = __expf(topv[e] - topv[0]); sumw += w[e]; }
    float inv = 1.0f / sumw;

    if (lane < 16) {
        float wf = 0.0f;
        #pragma unroll
        for (int e = 0; e < 10; ++e) {
            int m  = topi[e] >> 4;
            int ti2 = 48 + (topi[e] & 15);
            wf = fmaf(w[e] * inv, x[(m*TT + ti2)*FF + lane], wf);
        }
        float hid = b1[lane];
        #pragma unroll
        for (int f = 0; f < 16; ++f)
            hid = fmaf(W1[lane*16 + f], __shfl_sync(0xffffu, wf, f), hid);
        hid = hid > 0.0f ? hid : 0.01f * hid;
        float val = hid * W2[lane];
        #pragma unroll
        for (int off = 8; off; off >>= 1)
            val += __shfl_xor_sync(0xffffu, val, off);
        if (lane == 0) out[n] = val + b2[0];
    }
}

// ============================ launch ============================
extern "C" void kernel_launch(void* const* d_in, const int* in_sizes, int n_in,
                              void* d_out, int out_size)
{
    const float* x   = (const float*)d_in[0];
    const float* Wih = (const float*)d_in[1];
    const float* Whh = (const float*)d_in[2];
    const float* bih = (const float*)d_in[3];
    const float* bhh = (const float*)d_in[4];
    const float* Wq  = (const float*)d_in[5];
    const float* Wk  = (const float*)d_in[6];
    const float* W1  = (const float*)d_in[7];
    const float* b1  = (const float*)d_in[8];
    const float* W2  = (const float*)d_in[9];
    const float* b2  = (const float*)d_in[10];
    float* out = (float*)d_out;

    const int gru_smem = GRU_SMEM_FLOATS * 4;
    cudaFuncSetAttribute(gru_kernel, cudaFuncAttributeMaxDynamicSharedMemorySize, gru_smem);
    cudaFuncSetAttribute(scores_topk_kernel, cudaFuncAttributeMaxDynamicSharedMemorySize, K3_SMEM_BYTES);

    gru_kernel<<<NN/16, 256, gru_smem>>>(x, Wih, Whh, bih, bhh, Wq, Wk);
    dim3 g3(NN/64, KBLOCKS);
    scores_topk_kernel<<<g3, 256, K3_SMEM_BYTES>>>();
    final_kernel<<<NN/8, 256>>>(x, W1, b1, W2, b2, out);
}